// round 16
// baseline (speedup 1.0000x reference)
#include <cuda_runtime.h>
#include <math.h>

// Problem constants (fixed by the reference: B=16, N=4096, C=21)
#define BB      16
#define NN      4096
#define CC      21
#define SLICES  8                   // target slices per batch (grid.y), 512 targets each
#define PSPLIT  16                  // pred chunks per batch (grid.z)
#define PPTS    (NN / PSPLIT)       // 256 pred points per chunk
#define CPAIR   (PPTS / 2)          // 128 pred pairs per chunk (4 KB smem)
#define NTHR    128
#define NWRITER (BB * SLICES)       // 128

// Scratch (device globals; zero-initialized; every entry reset each run)
__device__ unsigned g_best[BB * NN];   // monotonic-encoded running max scores
__device__ float    g_part[NWRITER];   // per (batch,slice) loss partials
__device__ unsigned g_cnt [NWRITER];   // per-slice sibling counters
__device__ unsigned g_done;            // global writer counter

typedef unsigned long long ull;

// ---- packed f32x2 helpers (sm_100+) ----
__device__ __forceinline__ ull fma2(ull a, ull b, ull c) {
    ull d;
    asm("fma.rn.f32x2 %0, %1, %2, %3;" : "=l"(d) : "l"(a), "l"(b), "l"(c));
    return d;
}
__device__ __forceinline__ ull pack2(float x) {
    ull d;
    asm("mov.b64 %0, {%1, %1};" : "=l"(d) : "r"(__float_as_uint(x)));
    return d;
}
__device__ __forceinline__ ull packab(float a, float b) {
    ull d;
    asm("mov.b64 %0, {%1, %2};" : "=l"(d) : "r"(__float_as_uint(a)), "r"(__float_as_uint(b)));
    return d;
}
__device__ __forceinline__ float lo2(ull v) { return __uint_as_float((unsigned)(v & 0xffffffffull)); }
__device__ __forceinline__ float hi2(ull v) { return __uint_as_float((unsigned)(v >> 32)); }

// order-preserving float <-> uint (zero encodes below every finite value's code)
__device__ __forceinline__ unsigned enc_f(float f) {
    const unsigned b = __float_as_uint(f);
    return (b & 0x80000000u) ? ~b : (b | 0x80000000u);
}
__device__ __forceinline__ float dec_f(unsigned u) {
    const unsigned b = (u & 0x80000000u) ? (u ^ 0x80000000u) : ~u;
    return __uint_as_float(b);
}

__device__ __forceinline__ unsigned atom_inc_acqrel(unsigned* p) {
    unsigned old;
    asm volatile("atom.acq_rel.gpu.global.add.u32 %0, [%1], %2;"
                 : "=r"(old) : "l"(p), "r"(1u) : "memory");
    return old;
}
__device__ __forceinline__ void red_max_u32(unsigned* p, unsigned v) {
    asm volatile("red.global.max.u32 [%0], %1;" :: "l"(p), "r"(v) : "memory");
}

// sym_flags layout sniff (bool array upcast by harness: int32 / float32 / uint8)
__device__ __forceinline__ int sniff_mode(const void* p) {
    const unsigned* w = (const unsigned*)p;
    bool is_i32 = true, is_f32 = true;
#pragma unroll
    for (int i = 0; i < CC; i++) {
        const unsigned v = w[i];
        if (v > 1u) is_i32 = false;
        if (v != 0u && v != 0x3F800000u) is_f32 = false;
    }
    return (is_i32 || is_f32) ? 0 : 1;
}
__device__ __forceinline__ bool read_flag(const void* p, int lb, int mode) {
    if (mode == 0) return ((const unsigned*)p)[lb] != 0u;
    return ((const unsigned char*)p)[lb] != 0;
}

// ============================================================================
// ONE kernel. grid (BB, SLICES, PSPLIT) = 2048 blocks, 128 threads, 4KB smem.
// R15 body (4 targets/thread, packed-FMA inner loop) with PSPLIT 32->16:
// halves per-block setup share and red.max/atomic traffic. The fma-pipe
// saturation model predicts this is NEUTRAL (we are at the dense roofline).
//  sym batch:   block scans pred chunk z (256 rotated preds in smem) for its
//               512 targets (4/thread); red.max publishes encoded scores into
//               g_best. Last of 16 siblings combines, sqrts, writes slice
//               partial, resets its g_best entries.
//  non-sym:     z==0 block computes the direct loss for its 512-pt slice.
//  last writer reduces 128 partials -> scalar loss, resets.
// ============================================================================
__global__ void __launch_bounds__(NTHR, 8)
fused_kernel(const float* __restrict__ pred_r,
             const float* __restrict__ gt_r,
             const float* __restrict__ points,
             const float* __restrict__ mesh_diameter,
             const int*   __restrict__ labels,
             const void*  __restrict__ sym_flags,
             float*       __restrict__ out) {
    __shared__ ulonglong2 smA[CPAIR];    // {p0x,p1x} , {p0y,p1y}
    __shared__ ulonglong2 smB[CPAIR];    // {p0z,p1z} , {nh0,nh1}
    __shared__ float red[NTHR / 32];
    __shared__ int   s_sym, s_combine, s_last;

    const int b     = blockIdx.x;
    const int y     = blockIdx.y;
    const int z     = blockIdx.z;
    const int tid   = threadIdx.x;
    const int slice = b * SLICES + y;

    if (tid == 0) {
        const int m = sniff_mode(sym_flags);
        s_sym = read_flag(sym_flags, labels[b], m) ? 1 : 0;
    }
    __syncthreads();

    float part  = 0.0f;
    bool  wrote_part = false;

    if (s_sym) {
        float R[9], G[9];
#pragma unroll
        for (int i = 0; i < 9; i++) {
            R[i] = __ldg(pred_r + b * 9 + i);
            G[i] = __ldg(gt_r   + b * 9 + i);
        }

        // ---- own 4 targets rotated by gt_r ----
        float tw[4]; ull txp[4], typ[4], tzp[4];
#pragma unroll
        for (int k = 0; k < 4; k++) {
            const int n = y * 512 + k * 128 + tid;
            const float* p = points + ((long)b * NN + n) * 3;
            const float px = p[0], py = p[1], pz = p[2];
            const float tx = fmaf(G[0], px, fmaf(G[1], py, G[2] * pz));
            const float ty = fmaf(G[3], px, fmaf(G[4], py, G[5] * pz));
            const float tz = fmaf(G[6], px, fmaf(G[7], py, G[8] * pz));
            tw[k]  = tx * tx + ty * ty + tz * tz;
            txp[k] = pack2(tx); typ[k] = pack2(ty); tzp[k] = pack2(tz);
        }

        // ---- fill: rotate this chunk's 256 preds into interleaved smem ----
        // CPAIR == NTHR: exactly one pair per thread.
        {
            const float2* pts2 = (const float2*)(points + ((long)b * NN + z * PPTS) * 3);
            const int q = tid;
            const float2 f0 = pts2[3 * q + 0];   // p0x p0y
            const float2 f1 = pts2[3 * q + 1];   // p0z p1x
            const float2 f2 = pts2[3 * q + 2];   // p1y p1z

            const float ax = fmaf(R[0], f0.x, fmaf(R[1], f0.y, R[2] * f1.x));
            const float ay = fmaf(R[3], f0.x, fmaf(R[4], f0.y, R[5] * f1.x));
            const float az = fmaf(R[6], f0.x, fmaf(R[7], f0.y, R[8] * f1.x));
            const float bx = fmaf(R[0], f1.y, fmaf(R[1], f2.x, R[2] * f2.y));
            const float by = fmaf(R[3], f1.y, fmaf(R[4], f2.x, R[5] * f2.y));
            const float bz = fmaf(R[6], f1.y, fmaf(R[7], f2.x, R[8] * f2.y));
            const float na = -0.5f * (ax * ax + ay * ay + az * az);
            const float nb = -0.5f * (bx * bx + by * by + bz * bz);

            ulonglong2 A, Bv;
            A.x  = packab(ax, bx);
            A.y  = packab(ay, by);
            Bv.x = packab(az, bz);
            Bv.y = packab(na, nb);
            smA[q] = A;
            smB[q] = Bv;
        }
        __syncthreads();

        // ---- inner loop: max score over 128 pred pairs, 4 targets ----
        float best[4] = {-1e30f, -1e30f, -1e30f, -1e30f};
#pragma unroll 8
        for (int q = 0; q < CPAIR; q++) {
            const ulonglong2 A  = smA[q];
            const ulonglong2 Bv = smB[q];
#pragma unroll
            for (int k = 0; k < 4; k++) {
                ull u = fma2(tzp[k], Bv.x, Bv.y);
                u = fma2(typ[k], A.y, u);
                u = fma2(txp[k], A.x, u);
                best[k] = fmaxf(best[k], fmaxf(lo2(u), hi2(u)));
            }
        }

        // ---- publish via red.max; last sibling combines ----
#pragma unroll
        for (int k = 0; k < 4; k++)
            red_max_u32(&g_best[b * NN + y * 512 + k * 128 + tid], enc_f(best[k]));
        if (tid == 0) {
            const unsigned old = atom_inc_acqrel(&g_cnt[slice]);
            s_combine = (old == PSPLIT - 1) ? 1 : 0;
        }
        __syncthreads();

        if (s_combine) {
#pragma unroll
            for (int k = 0; k < 4; k++) {
                const int idx = b * NN + y * 512 + k * 128 + tid;
                const unsigned u = g_best[idx];
                part += sqrtf(fmaxf(fmaf(-2.0f, dec_f(u), tw[k]), 0.0f));
                g_best[idx] = 0u;   // reset for next graph replay
            }
            if (tid == 0) g_cnt[slice] = 0;
            wrote_part = true;
        }
    } else {
        if (z != 0) return;     // only one sibling does the direct loss
        float R[9], G[9];
#pragma unroll
        for (int i = 0; i < 9; i++) {
            R[i] = __ldg(pred_r + b * 9 + i);
            G[i] = __ldg(gt_r   + b * 9 + i);
        }
#pragma unroll
        for (int k = 0; k < 4; k++) {
            const int n = y * 512 + k * 128 + tid;
            const float* p = points + ((long)b * NN + n) * 3;
            const float px = p[0], py = p[1], pz = p[2];
            const float dx = fmaf(R[0] - G[0], px, fmaf(R[1] - G[1], py, (R[2] - G[2]) * pz));
            const float dy = fmaf(R[3] - G[3], px, fmaf(R[4] - G[4], py, (R[5] - G[5]) * pz));
            const float dz = fmaf(R[6] - G[6], px, fmaf(R[7] - G[7], py, (R[8] - G[8]) * pz));
            part += sqrtf(dx * dx + dy * dy + dz * dz);
        }
        wrote_part = true;
    }

    if (!wrote_part) return;

    // ---- block reduction of part (128 threads) -> g_part[slice] ----
#pragma unroll
    for (int o = 16; o > 0; o >>= 1) part += __shfl_down_sync(0xffffffffu, part, o);
    if ((tid & 31) == 0) red[tid >> 5] = part;
    __syncthreads();
    if (tid == 0) {
        float v = 0.0f;
#pragma unroll
        for (int w = 0; w < NTHR / 32; w++) v += red[w];
        g_part[slice] = v;
        const unsigned old = atom_inc_acqrel(&g_done);
        s_last = (old == (unsigned)(NWRITER - 1)) ? 1 : 0;
    }
    __syncthreads();

    // ---- last writer: final reduction over all (batch, slice) partials ----
    if (s_last) {
        if (tid < 32) {
            float v = 0.0f;
            if (tid < BB) {
                float sum = 0.0f;
#pragma unroll
                for (int s = 0; s < SLICES; s++) sum += g_part[tid * SLICES + s];
                v = sum * (1.0f / NN) / __ldg(mesh_diameter + labels[tid]);
            }
#pragma unroll
            for (int o = 16; o > 0; o >>= 1) v += __shfl_down_sync(0xffffffffu, v, o);
            if (tid == 0) {
                *out = v * (1.0f / BB);
                g_done = 0;   // reset for next graph replay (deterministic)
            }
        }
    }
}

// ============================================================================
extern "C" void kernel_launch(void* const* d_in, const int* in_sizes, int n_in,
                              void* d_out, int out_size) {
    const float* pred_r        = (const float*)d_in[0];
    const float* gt_r          = (const float*)d_in[1];
    const float* points        = (const float*)d_in[2];
    const float* mesh_diameter = (const float*)d_in[3];
    const int*   labels        = (const int*)d_in[4];
    const void*  sym_flags     = d_in[5];

    fused_kernel<<<dim3(BB, SLICES, PSPLIT), NTHR>>>(
        pred_r, gt_r, points, mesh_diameter, labels, sym_flags, (float*)d_out);
}

// round 17
// speedup vs baseline: 1.1658x; 1.1658x over previous
#include <cuda_runtime.h>
#include <math.h>

// Problem constants (fixed by the reference: B=16, N=4096, C=21)
#define BB      16
#define NN      4096
#define CC      21
#define SLICES  8                   // target slices per batch (grid.y), 512 targets each
#define PSPLIT  32                  // pred chunks per batch (grid.z)
#define PPTS    (NN / PSPLIT)       // 128 pred points per chunk
#define CPAIR   (PPTS / 2)          // 64 pred pairs per chunk (2 KB smem)
#define NTHR    128
#define NWRITER (BB * SLICES)       // 128

// Scratch (device globals; zero-initialized; every entry reset each run)
__device__ unsigned g_best[BB * NN];   // monotonic-encoded running max scores
__device__ float    g_part[NWRITER];   // per (batch,slice) loss partials
__device__ unsigned g_cnt [NWRITER];   // per-slice sibling counters
__device__ unsigned g_done;            // global writer counter

typedef unsigned long long ull;

// ---- packed f32x2 helpers (sm_100+) ----
__device__ __forceinline__ ull fma2(ull a, ull b, ull c) {
    ull d;
    asm("fma.rn.f32x2 %0, %1, %2, %3;" : "=l"(d) : "l"(a), "l"(b), "l"(c));
    return d;
}
__device__ __forceinline__ ull pack2(float x) {
    ull d;
    asm("mov.b64 %0, {%1, %1};" : "=l"(d) : "r"(__float_as_uint(x)));
    return d;
}
__device__ __forceinline__ ull packab(float a, float b) {
    ull d;
    asm("mov.b64 %0, {%1, %2};" : "=l"(d) : "r"(__float_as_uint(a)), "r"(__float_as_uint(b)));
    return d;
}
__device__ __forceinline__ float lo2(ull v) { return __uint_as_float((unsigned)(v & 0xffffffffull)); }
__device__ __forceinline__ float hi2(ull v) { return __uint_as_float((unsigned)(v >> 32)); }

// order-preserving float <-> uint (zero encodes below every finite value's code)
__device__ __forceinline__ unsigned enc_f(float f) {
    const unsigned b = __float_as_uint(f);
    return (b & 0x80000000u) ? ~b : (b | 0x80000000u);
}
__device__ __forceinline__ float dec_f(unsigned u) {
    const unsigned b = (u & 0x80000000u) ? (u ^ 0x80000000u) : ~u;
    return __uint_as_float(b);
}

__device__ __forceinline__ unsigned atom_inc_acqrel(unsigned* p) {
    unsigned old;
    asm volatile("atom.acq_rel.gpu.global.add.u32 %0, [%1], %2;"
                 : "=r"(old) : "l"(p), "r"(1u) : "memory");
    return old;
}
__device__ __forceinline__ void red_max_u32(unsigned* p, unsigned v) {
    asm volatile("red.global.max.u32 [%0], %1;" :: "l"(p), "r"(v) : "memory");
}

// sym_flags layout sniff (bool array upcast by harness: int32 / float32 / uint8)
__device__ __forceinline__ int sniff_mode(const void* p) {
    const unsigned* w = (const unsigned*)p;
    bool is_i32 = true, is_f32 = true;
#pragma unroll
    for (int i = 0; i < CC; i++) {
        const unsigned v = w[i];
        if (v > 1u) is_i32 = false;
        if (v != 0u && v != 0x3F800000u) is_f32 = false;
    }
    return (is_i32 || is_f32) ? 0 : 1;
}
__device__ __forceinline__ bool read_flag(const void* p, int lb, int mode) {
    if (mode == 0) return ((const unsigned*)p)[lb] != 0u;
    return ((const unsigned char*)p)[lb] != 0;
}

// ============================================================================
// ONE kernel. grid (BB, SLICES, PSPLIT) = 4096 blocks, 128 threads, 2KB smem.
// Converged configuration (R15): 4 targets/thread packed-FMA inner loop at
// PSPLIT=32 — measured at the dense fma-pipe roofline (~24 us floor).
//  sym batch:   block scans pred chunk z (128 rotated preds in smem) for its
//               512 targets (4/thread); red.max publishes encoded scores into
//               g_best. Last of 32 siblings combines, sqrts, writes slice
//               partial, resets its g_best entries.
//  non-sym:     z==0 block computes the direct loss for its 512-pt slice.
//  last writer reduces 128 partials -> scalar loss, resets.
// ============================================================================
__global__ void __launch_bounds__(NTHR, 8)
fused_kernel(const float* __restrict__ pred_r,
             const float* __restrict__ gt_r,
             const float* __restrict__ points,
             const float* __restrict__ mesh_diameter,
             const int*   __restrict__ labels,
             const void*  __restrict__ sym_flags,
             float*       __restrict__ out) {
    __shared__ ulonglong2 smA[CPAIR];    // {p0x,p1x} , {p0y,p1y}
    __shared__ ulonglong2 smB[CPAIR];    // {p0z,p1z} , {nh0,nh1}
    __shared__ float red[NTHR / 32];
    __shared__ int   s_sym, s_combine, s_last;

    const int b     = blockIdx.x;
    const int y     = blockIdx.y;
    const int z     = blockIdx.z;
    const int tid   = threadIdx.x;
    const int slice = b * SLICES + y;

    if (tid == 0) {
        const int m = sniff_mode(sym_flags);
        s_sym = read_flag(sym_flags, labels[b], m) ? 1 : 0;
    }
    __syncthreads();

    float part  = 0.0f;
    bool  wrote_part = false;

    if (s_sym) {
        float R[9], G[9];
#pragma unroll
        for (int i = 0; i < 9; i++) {
            R[i] = __ldg(pred_r + b * 9 + i);
            G[i] = __ldg(gt_r   + b * 9 + i);
        }

        // ---- own 4 targets rotated by gt_r ----
        float tw[4]; ull txp[4], typ[4], tzp[4];
#pragma unroll
        for (int k = 0; k < 4; k++) {
            const int n = y * 512 + k * 128 + tid;
            const float* p = points + ((long)b * NN + n) * 3;
            const float px = p[0], py = p[1], pz = p[2];
            const float tx = fmaf(G[0], px, fmaf(G[1], py, G[2] * pz));
            const float ty = fmaf(G[3], px, fmaf(G[4], py, G[5] * pz));
            const float tz = fmaf(G[6], px, fmaf(G[7], py, G[8] * pz));
            tw[k]  = tx * tx + ty * ty + tz * tz;
            txp[k] = pack2(tx); typ[k] = pack2(ty); tzp[k] = pack2(tz);
        }

        // ---- fill: rotate this chunk's 128 preds into interleaved smem ----
        if (tid < CPAIR) {
            const float2* pts2 = (const float2*)(points + ((long)b * NN + z * PPTS) * 3);
            const int q = tid;
            const float2 f0 = pts2[3 * q + 0];   // p0x p0y
            const float2 f1 = pts2[3 * q + 1];   // p0z p1x
            const float2 f2 = pts2[3 * q + 2];   // p1y p1z

            const float ax = fmaf(R[0], f0.x, fmaf(R[1], f0.y, R[2] * f1.x));
            const float ay = fmaf(R[3], f0.x, fmaf(R[4], f0.y, R[5] * f1.x));
            const float az = fmaf(R[6], f0.x, fmaf(R[7], f0.y, R[8] * f1.x));
            const float bx = fmaf(R[0], f1.y, fmaf(R[1], f2.x, R[2] * f2.y));
            const float by = fmaf(R[3], f1.y, fmaf(R[4], f2.x, R[5] * f2.y));
            const float bz = fmaf(R[6], f1.y, fmaf(R[7], f2.x, R[8] * f2.y));
            const float na = -0.5f * (ax * ax + ay * ay + az * az);
            const float nb = -0.5f * (bx * bx + by * by + bz * bz);

            ulonglong2 A, Bv;
            A.x  = packab(ax, bx);
            A.y  = packab(ay, by);
            Bv.x = packab(az, bz);
            Bv.y = packab(na, nb);
            smA[q] = A;
            smB[q] = Bv;
        }
        __syncthreads();

        // ---- inner loop: max score over 64 pred pairs, 4 targets ----
        float best[4] = {-1e30f, -1e30f, -1e30f, -1e30f};
#pragma unroll 8
        for (int q = 0; q < CPAIR; q++) {
            const ulonglong2 A  = smA[q];
            const ulonglong2 Bv = smB[q];
#pragma unroll
            for (int k = 0; k < 4; k++) {
                ull u = fma2(tzp[k], Bv.x, Bv.y);
                u = fma2(typ[k], A.y, u);
                u = fma2(txp[k], A.x, u);
                best[k] = fmaxf(best[k], fmaxf(lo2(u), hi2(u)));
            }
        }

        // ---- publish via red.max; last sibling combines ----
#pragma unroll
        for (int k = 0; k < 4; k++)
            red_max_u32(&g_best[b * NN + y * 512 + k * 128 + tid], enc_f(best[k]));
        if (tid == 0) {
            const unsigned old = atom_inc_acqrel(&g_cnt[slice]);
            s_combine = (old == PSPLIT - 1) ? 1 : 0;
        }
        __syncthreads();

        if (s_combine) {
#pragma unroll
            for (int k = 0; k < 4; k++) {
                const int idx = b * NN + y * 512 + k * 128 + tid;
                const unsigned u = g_best[idx];
                part += sqrtf(fmaxf(fmaf(-2.0f, dec_f(u), tw[k]), 0.0f));
                g_best[idx] = 0u;   // reset for next graph replay
            }
            if (tid == 0) g_cnt[slice] = 0;
            wrote_part = true;
        }
    } else {
        if (z != 0) return;     // only one sibling does the direct loss
        float R[9], G[9];
#pragma unroll
        for (int i = 0; i < 9; i++) {
            R[i] = __ldg(pred_r + b * 9 + i);
            G[i] = __ldg(gt_r   + b * 9 + i);
        }
#pragma unroll
        for (int k = 0; k < 4; k++) {
            const int n = y * 512 + k * 128 + tid;
            const float* p = points + ((long)b * NN + n) * 3;
            const float px = p[0], py = p[1], pz = p[2];
            const float dx = fmaf(R[0] - G[0], px, fmaf(R[1] - G[1], py, (R[2] - G[2]) * pz));
            const float dy = fmaf(R[3] - G[3], px, fmaf(R[4] - G[4], py, (R[5] - G[5]) * pz));
            const float dz = fmaf(R[6] - G[6], px, fmaf(R[7] - G[7], py, (R[8] - G[8]) * pz));
            part += sqrtf(dx * dx + dy * dy + dz * dz);
        }
        wrote_part = true;
    }

    if (!wrote_part) return;

    // ---- block reduction of part (128 threads) -> g_part[slice] ----
#pragma unroll
    for (int o = 16; o > 0; o >>= 1) part += __shfl_down_sync(0xffffffffu, part, o);
    if ((tid & 31) == 0) red[tid >> 5] = part;
    __syncthreads();
    if (tid == 0) {
        float v = 0.0f;
#pragma unroll
        for (int w = 0; w < NTHR / 32; w++) v += red[w];
        g_part[slice] = v;
        const unsigned old = atom_inc_acqrel(&g_done);
        s_last = (old == (unsigned)(NWRITER - 1)) ? 1 : 0;
    }
    __syncthreads();

    // ---- last writer: final reduction over all (batch, slice) partials ----
    if (s_last) {
        if (tid < 32) {
            float v = 0.0f;
            if (tid < BB) {
                float sum = 0.0f;
#pragma unroll
                for (int s = 0; s < SLICES; s++) sum += g_part[tid * SLICES + s];
                v = sum * (1.0f / NN) / __ldg(mesh_diameter + labels[tid]);
            }
#pragma unroll
            for (int o = 16; o > 0; o >>= 1) v += __shfl_down_sync(0xffffffffu, v, o);
            if (tid == 0) {
                *out = v * (1.0f / BB);
                g_done = 0;   // reset for next graph replay (deterministic)
            }
        }
    }
}

// ============================================================================
extern "C" void kernel_launch(void* const* d_in, const int* in_sizes, int n_in,
                              void* d_out, int out_size) {
    const float* pred_r        = (const float*)d_in[0];
    const float* gt_r          = (const float*)d_in[1];
    const float* points        = (const float*)d_in[2];
    const float* mesh_diameter = (const float*)d_in[3];
    const int*   labels        = (const int*)d_in[4];
    const void*  sym_flags     = d_in[5];

    fused_kernel<<<dim3(BB, SLICES, PSPLIT), NTHR>>>(
        pred_r, gt_r, points, mesh_diameter, labels, sym_flags, (float*)d_out);
}